// round 2
// baseline (speedup 1.0000x reference)
#include <cuda_runtime.h>

#define NN   50000
#define EE   800000
#define INC  128
#define OUTC 32
#define HH   4
#define EDIM 16
#define HO   128          // H*OUT
#define ENF  (EE + NN)    // edges + self loops = 850000
#define SLOPE 0.2f

// ---------------- scratch (device globals; no allocation allowed) ----------
__device__ float    g_xl[(size_t)NN * HO];       // x @ W_l + b_l   (25.6 MB)
__device__ float    g_xr[(size_t)NN * HO];       // x @ W_r + b_r   (25.6 MB)
__device__ float    g_deg[NN];                   // in-degree
__device__ float    g_asum[(size_t)NN * EDIM];   // scatter-sum of edge attrs
__device__ float    g_denom[(size_t)NN * HH];    // softmax denominators
__device__ float4   g_accum[(size_t)NN * OUTC];  // sum exp(s) * x_l[src]  (25.6 MB)

// ---------------- helpers --------------------------------------------------
__device__ __forceinline__ float lrelu(float v) { return v > 0.f ? v : SLOPE * v; }

__device__ __forceinline__ void red_add_v4(float4* addr, float4 v) {
    asm volatile("red.global.add.v4.f32 [%0], {%1,%2,%3,%4};"
                 :: "l"(addr), "f"(v.x), "f"(v.y), "f"(v.z), "f"(v.w)
                 : "memory");
}

// ---------------- kernel 1: zero scratch -----------------------------------
__global__ void zero_kernel() {
    long i = (long)blockIdx.x * blockDim.x + threadIdx.x;
    long stride = (long)gridDim.x * blockDim.x;
    float* acc = (float*)g_accum;
    for (long j = i; j < (long)NN * HO; j += stride) acc[j] = 0.f;
    for (long j = i; j < (long)NN * HH; j += stride) g_denom[j] = 0.f;
    for (long j = i; j < (long)NN; j += stride) g_deg[j] = 0.f;
    for (long j = i; j < (long)NN * EDIM; j += stride) g_asum[j] = 0.f;
}

// ---------------- kernel 2: degree + attr scatter-sum ----------------------
__global__ void deg_attr_kernel(const int* __restrict__ ei,
                                const float* __restrict__ eattr) {
    long tid = (long)blockIdx.x * blockDim.x + threadIdx.x;
    if (tid >= (long)EE * EDIM) return;
    int e = (int)(tid >> 4);
    int d = (int)(tid & 15);
    int t = ei[EE + e];
    atomicAdd(&g_asum[(size_t)t * EDIM + d], eattr[tid]);
    if (d == 0) atomicAdd(&g_deg[t], 1.f);
}

// ---------------- kernel 3: x_l / x_r GEMMs (64-row tile, 256 threads) -----
__global__ void gemm_xlr(const float* __restrict__ x,
                         const float* __restrict__ Wl, const float* __restrict__ bl,
                         const float* __restrict__ Wr, const float* __restrict__ br) {
    __shared__ float xs[64][INC];
    int row0 = blockIdx.x * 64;
    int tid = threadIdx.x;

    const float4* x4 = (const float4*)x;
    for (int i = tid; i < 64 * 32; i += 256) {
        int r = i >> 5, c = i & 31;
        float4 v = make_float4(0.f, 0.f, 0.f, 0.f);
        if (row0 + r < NN) v = x4[(long)(row0 + r) * 32 + c];
        ((float4*)xs[r])[c] = v;
    }
    __syncthreads();

    int tx = tid & 31, ty = tid >> 5;        // tx: 4-col group, ty: row phase
    float4 aL[8], aR[8];
#pragma unroll
    for (int r = 0; r < 8; r++) {
        aL[r] = make_float4(0.f, 0.f, 0.f, 0.f);
        aR[r] = make_float4(0.f, 0.f, 0.f, 0.f);
    }
    const float4* Wl4 = (const float4*)Wl;
    const float4* Wr4 = (const float4*)Wr;
    for (int k = 0; k < INC; k++) {
        float4 wl = Wl4[k * 32 + tx];
        float4 wr = Wr4[k * 32 + tx];
#pragma unroll
        for (int r = 0; r < 8; r++) {
            float xv = xs[ty + r * 8][k];
            aL[r].x = fmaf(xv, wl.x, aL[r].x); aL[r].y = fmaf(xv, wl.y, aL[r].y);
            aL[r].z = fmaf(xv, wl.z, aL[r].z); aL[r].w = fmaf(xv, wl.w, aL[r].w);
            aR[r].x = fmaf(xv, wr.x, aR[r].x); aR[r].y = fmaf(xv, wr.y, aR[r].y);
            aR[r].z = fmaf(xv, wr.z, aR[r].z); aR[r].w = fmaf(xv, wr.w, aR[r].w);
        }
    }
    float4 blv = ((const float4*)bl)[tx];
    float4 brv = ((const float4*)br)[tx];
#pragma unroll
    for (int r = 0; r < 8; r++) {
        int row = row0 + ty + r * 8;
        if (row < NN) {
            float4 ol = make_float4(aL[r].x + blv.x, aL[r].y + blv.y,
                                    aL[r].z + blv.z, aL[r].w + blv.w);
            float4 orr = make_float4(aR[r].x + brv.x, aR[r].y + brv.y,
                                     aR[r].z + brv.z, aR[r].w + brv.w);
            ((float4*)g_xl)[(long)row * 32 + tx] = ol;
            ((float4*)g_xr)[(long)row * 32 + tx] = orr;
        }
    }
}

// ---------------- kernel 4: FUSED edge pass --------------------------------
// one warp per edge; lane owns channel-quad `lane` (4 contiguous channels).
// Computes GATv2 score, ex = exp(score) (no max-subtraction: mathematically
// identical alpha, scores bounded ~|13| so no overflow), then scatters
// denom += ex and accum += ex * x_l[src] in the same pass (x_l already in regs).
__global__ void __launch_bounds__(256)
edge_fused_kernel(const int* __restrict__ ei,
                  const float* __restrict__ eattr,
                  const float* __restrict__ We,
                  const float* __restrict__ att) {
    int tid = threadIdx.x;
    int warp = tid >> 5, lane = tid & 31;
    long ew = (long)blockIdx.x * 8 + warp;
    if (ew >= ENF) return;

    // W_e slice for this lane's channel quad: 16 x float4 in registers.
    // All threads load the same 8KB -> L1 broadcast, loaded once per thread.
    const float4* We4 = (const float4*)We;
    float4 w[EDIM];
#pragma unroll
    for (int d = 0; d < EDIM; d++) w[d] = We4[d * 32 + lane];
    float4 av = ((const float4*)att)[lane];

    int s, t;
    const float* ap;
    float inv;
    if (ew < EE) {
        s = ei[ew];
        t = ei[EE + ew];
        ap = &eattr[ew * EDIM];
        inv = 1.f;
    } else {
        int n = (int)(ew - EE);
        s = n; t = n;
        ap = &g_asum[(size_t)n * EDIM];
        inv = 1.f / fmaxf(g_deg[n], 1.f);
    }

    // gathers (512B each, warp-contiguous)
    float4 xl = __ldg(&((const float4*)g_xl)[(long)s * 32 + lane]);
    float4 xr = __ldg(&((const float4*)g_xr)[(long)t * 32 + lane]);

    // edge projection e = attr @ W_e : 4 uniform LDG.128 + 16 FMA4
    float4 e = make_float4(0.f, 0.f, 0.f, 0.f);
    const float4* ap4 = (const float4*)ap;
#pragma unroll
    for (int q = 0; q < 4; q++) {
        float4 a4 = __ldg(&ap4[q]);
        float ad;
        ad = a4.x * inv;
        e.x = fmaf(ad, w[q*4+0].x, e.x); e.y = fmaf(ad, w[q*4+0].y, e.y);
        e.z = fmaf(ad, w[q*4+0].z, e.z); e.w = fmaf(ad, w[q*4+0].w, e.w);
        ad = a4.y * inv;
        e.x = fmaf(ad, w[q*4+1].x, e.x); e.y = fmaf(ad, w[q*4+1].y, e.y);
        e.z = fmaf(ad, w[q*4+1].z, e.z); e.w = fmaf(ad, w[q*4+1].w, e.w);
        ad = a4.z * inv;
        e.x = fmaf(ad, w[q*4+2].x, e.x); e.y = fmaf(ad, w[q*4+2].y, e.y);
        e.z = fmaf(ad, w[q*4+2].z, e.z); e.w = fmaf(ad, w[q*4+2].w, e.w);
        ad = a4.w * inv;
        e.x = fmaf(ad, w[q*4+3].x, e.x); e.y = fmaf(ad, w[q*4+3].y, e.y);
        e.z = fmaf(ad, w[q*4+3].z, e.z); e.w = fmaf(ad, w[q*4+3].w, e.w);
    }

    // score = att . lrelu(xl + xr + e), per head (8 lanes per head)
    float4 m = make_float4(lrelu(xl.x + xr.x + e.x), lrelu(xl.y + xr.y + e.y),
                           lrelu(xl.z + xr.z + e.z), lrelu(xl.w + xr.w + e.w));
    float p = m.x * av.x + m.y * av.y + m.z * av.z + m.w * av.w;
    p += __shfl_xor_sync(0xffffffffu, p, 4);
    p += __shfl_xor_sync(0xffffffffu, p, 2);
    p += __shfl_xor_sync(0xffffffffu, p, 1);
    // every lane now holds its head's full score
    float ex = __expf(p) ;           // fast exp; see note below
    ex = expf(p);                    // use precise expf to stay well under 1e-3

    if ((lane & 7) == 0)
        atomicAdd(&g_denom[(size_t)t * HH + (lane >> 3)], ex);

    red_add_v4(&g_accum[(long)t * 32 + lane],
               make_float4(ex * xl.x, ex * xl.y, ex * xl.z, ex * xl.w));
}

// ---------------- kernel 5: finalize (head mean + bias + LeakyReLU) --------
__global__ void finalize_kernel(const float* __restrict__ bias,
                                float* __restrict__ out) {
    int idx = blockIdx.x * blockDim.x + threadIdx.x;
    if (idx >= NN * OUTC) return;
    int n = idx >> 5, c = idx & 31;
    const float* acc = (const float*)g_accum;
    float sum = 0.f;
#pragma unroll
    for (int hh = 0; hh < HH; hh++)
        sum += acc[(size_t)n * HO + hh * OUTC + c] / g_denom[(size_t)n * HH + hh];
    float o = sum * 0.25f + bias[c];
    out[idx] = lrelu(o);
}

// ---------------- launch ---------------------------------------------------
extern "C" void kernel_launch(void* const* d_in, const int* in_sizes, int n_in,
                              void* d_out, int out_size) {
    const float* x     = (const float*)d_in[0];
    const int*   ei    = (const int*)  d_in[1];
    const float* eattr = (const float*)d_in[2];
    const float* Wl    = (const float*)d_in[3];
    const float* bl    = (const float*)d_in[4];
    const float* Wr    = (const float*)d_in[5];
    const float* br    = (const float*)d_in[6];
    const float* We    = (const float*)d_in[7];
    const float* att   = (const float*)d_in[8];
    const float* bias  = (const float*)d_in[9];
    float* out = (float*)d_out;

    zero_kernel<<<4096, 256>>>();
    deg_attr_kernel<<<((long)EE * EDIM + 255) / 256, 256>>>(ei, eattr);
    gemm_xlr<<<(NN + 63) / 64, 256>>>(x, Wl, bl, Wr, br);
    edge_fused_kernel<<<(ENF + 7) / 8, 256>>>(ei, eattr, We, att);
    finalize_kernel<<<(NN * OUTC + 255) / 256, 256>>>(bias, out);
}

// round 3
// speedup vs baseline: 1.0722x; 1.0722x over previous
#include <cuda_runtime.h>

#define NN   50000
#define EE   800000
#define INC  128
#define OUTC 32
#define HH   4
#define EDIM 16
#define HO   128          // H*OUT
#define ENF  (EE + NN)    // edges + self loops = 850000
#define SLOPE 0.2f

// ---------------- scratch (device globals; no allocation allowed) ----------
__device__ float    g_xl[(size_t)NN * HO];       // x @ W_l + b_l   (25.6 MB)
__device__ float    g_xr[(size_t)NN * HO];       // x @ W_r + b_r   (25.6 MB)
__device__ float    g_deg[NN];                   // in-degree
__device__ float    g_asum[(size_t)NN * EDIM];   // scatter-sum of edge attrs
__device__ float    g_denom[(size_t)NN * HH];    // softmax denominators
__device__ float4   g_accum[(size_t)NN * OUTC];  // sum exp(s) * x_l[src]  (25.6 MB)

// ---------------- helpers --------------------------------------------------
__device__ __forceinline__ float lrelu(float v) { return v > 0.f ? v : SLOPE * v; }

__device__ __forceinline__ void red_add_v4(float4* addr, float4 v) {
    asm volatile("red.global.add.v4.f32 [%0], {%1,%2,%3,%4};"
                 :: "l"(addr), "f"(v.x), "f"(v.y), "f"(v.z), "f"(v.w)
                 : "memory");
}

// ---------------- kernel 1: zero scratch -----------------------------------
__global__ void zero_kernel() {
    long i = (long)blockIdx.x * blockDim.x + threadIdx.x;
    long stride = (long)gridDim.x * blockDim.x;
    float* acc = (float*)g_accum;
    for (long j = i; j < (long)NN * HO; j += stride) acc[j] = 0.f;
    for (long j = i; j < (long)NN * HH; j += stride) g_denom[j] = 0.f;
    for (long j = i; j < (long)NN; j += stride) g_deg[j] = 0.f;
    for (long j = i; j < (long)NN * EDIM; j += stride) g_asum[j] = 0.f;
}

// ---------------- kernel 2: degree + attr scatter-sum (vectorized) ---------
__global__ void deg_attr_kernel(const int* __restrict__ ei,
                                const float* __restrict__ eattr) {
    int e = blockIdx.x * blockDim.x + threadIdx.x;
    if (e >= EE) return;
    int t = ei[EE + e];
    const float4* a4 = (const float4*)&eattr[(long)e * EDIM];
    float4* dst = &((float4*)g_asum)[(long)t * 4];
#pragma unroll
    for (int q = 0; q < 4; q++) red_add_v4(&dst[q], a4[q]);
    atomicAdd(&g_deg[t], 1.f);
}

// ---------------- kernel 3: x_l / x_r GEMMs (64-row tile, 256 threads) -----
__global__ void gemm_xlr(const float* __restrict__ x,
                         const float* __restrict__ Wl, const float* __restrict__ bl,
                         const float* __restrict__ Wr, const float* __restrict__ br) {
    __shared__ float xs[64][INC];
    int row0 = blockIdx.x * 64;
    int tid = threadIdx.x;

    const float4* x4 = (const float4*)x;
    for (int i = tid; i < 64 * 32; i += 256) {
        int r = i >> 5, c = i & 31;
        float4 v = make_float4(0.f, 0.f, 0.f, 0.f);
        if (row0 + r < NN) v = x4[(long)(row0 + r) * 32 + c];
        ((float4*)xs[r])[c] = v;
    }
    __syncthreads();

    int tx = tid & 31, ty = tid >> 5;
    float4 aL[8], aR[8];
#pragma unroll
    for (int r = 0; r < 8; r++) {
        aL[r] = make_float4(0.f, 0.f, 0.f, 0.f);
        aR[r] = make_float4(0.f, 0.f, 0.f, 0.f);
    }
    const float4* Wl4 = (const float4*)Wl;
    const float4* Wr4 = (const float4*)Wr;
    for (int k = 0; k < INC; k++) {
        float4 wl = Wl4[k * 32 + tx];
        float4 wr = Wr4[k * 32 + tx];
#pragma unroll
        for (int r = 0; r < 8; r++) {
            float xv = xs[ty + r * 8][k];
            aL[r].x = fmaf(xv, wl.x, aL[r].x); aL[r].y = fmaf(xv, wl.y, aL[r].y);
            aL[r].z = fmaf(xv, wl.z, aL[r].z); aL[r].w = fmaf(xv, wl.w, aL[r].w);
            aR[r].x = fmaf(xv, wr.x, aR[r].x); aR[r].y = fmaf(xv, wr.y, aR[r].y);
            aR[r].z = fmaf(xv, wr.z, aR[r].z); aR[r].w = fmaf(xv, wr.w, aR[r].w);
        }
    }
    float4 blv = ((const float4*)bl)[tx];
    float4 brv = ((const float4*)br)[tx];
#pragma unroll
    for (int r = 0; r < 8; r++) {
        int row = row0 + ty + r * 8;
        if (row < NN) {
            float4 ol = make_float4(aL[r].x + blv.x, aL[r].y + blv.y,
                                    aL[r].z + blv.z, aL[r].w + blv.w);
            float4 orr = make_float4(aR[r].x + brv.x, aR[r].y + brv.y,
                                     aR[r].z + brv.z, aR[r].w + brv.w);
            ((float4*)g_xl)[(long)row * 32 + tx] = ol;
            ((float4*)g_xr)[(long)row * 32 + tx] = orr;
        }
    }
}

// ---------------- kernel 4: FUSED edge pass (persistent warps) -------------
// Fixed grid; each warp loads W_e/att into registers ONCE, then grid-stride
// loops over edges (~240 per warp). Lane owns channel-quad `lane`.
// No max-subtraction softmax (scores bounded, alpha identical).
__global__ void __launch_bounds__(256)
edge_fused_kernel(const int* __restrict__ ei,
                  const float* __restrict__ eattr,
                  const float* __restrict__ We,
                  const float* __restrict__ att) {
    int lane = threadIdx.x & 31;

    // per-lane W_e slice (16 x float4) + att quad, loaded once per thread
    const float4* We4 = (const float4*)We;
    float4 w[EDIM];
#pragma unroll
    for (int d = 0; d < EDIM; d++) w[d] = We4[d * 32 + lane];
    float4 av = ((const float4*)att)[lane];

    long gwarp  = (long)blockIdx.x * (blockDim.x >> 5) + (threadIdx.x >> 5);
    long nwarps = (long)gridDim.x * (blockDim.x >> 5);

#pragma unroll 2
    for (long ew = gwarp; ew < ENF; ew += nwarps) {
        int s, t;
        const float4* ap4;
        float inv;
        if (ew < EE) {
            s = __ldg(&ei[ew]);
            t = __ldg(&ei[EE + ew]);
            ap4 = (const float4*)&eattr[ew * EDIM];
            inv = 1.f;
        } else {
            int n = (int)(ew - EE);
            s = n; t = n;
            ap4 = (const float4*)&g_asum[(size_t)n * EDIM];
            inv = 1.f / fmaxf(g_deg[n], 1.f);
        }

        float4 xl = __ldg(&((const float4*)g_xl)[(long)s * 32 + lane]);
        float4 xr = __ldg(&((const float4*)g_xr)[(long)t * 32 + lane]);

        // e = attr @ W_e : 4 uniform LDG.128 + 16 FMA4
        float4 e = make_float4(0.f, 0.f, 0.f, 0.f);
#pragma unroll
        for (int q = 0; q < 4; q++) {
            float4 a4 = __ldg(&ap4[q]);
            float ad;
            ad = a4.x * inv;
            e.x = fmaf(ad, w[q*4+0].x, e.x); e.y = fmaf(ad, w[q*4+0].y, e.y);
            e.z = fmaf(ad, w[q*4+0].z, e.z); e.w = fmaf(ad, w[q*4+0].w, e.w);
            ad = a4.y * inv;
            e.x = fmaf(ad, w[q*4+1].x, e.x); e.y = fmaf(ad, w[q*4+1].y, e.y);
            e.z = fmaf(ad, w[q*4+1].z, e.z); e.w = fmaf(ad, w[q*4+1].w, e.w);
            ad = a4.z * inv;
            e.x = fmaf(ad, w[q*4+2].x, e.x); e.y = fmaf(ad, w[q*4+2].y, e.y);
            e.z = fmaf(ad, w[q*4+2].z, e.z); e.w = fmaf(ad, w[q*4+2].w, e.w);
            ad = a4.w * inv;
            e.x = fmaf(ad, w[q*4+3].x, e.x); e.y = fmaf(ad, w[q*4+3].y, e.y);
            e.z = fmaf(ad, w[q*4+3].z, e.z); e.w = fmaf(ad, w[q*4+3].w, e.w);
        }

        // score = att . lrelu(xl + xr + e), per head (8 lanes/head)
        float4 m = make_float4(lrelu(xl.x + xr.x + e.x), lrelu(xl.y + xr.y + e.y),
                               lrelu(xl.z + xr.z + e.z), lrelu(xl.w + xr.w + e.w));
        float p = m.x * av.x + m.y * av.y + m.z * av.z + m.w * av.w;
        p += __shfl_xor_sync(0xffffffffu, p, 4);
        p += __shfl_xor_sync(0xffffffffu, p, 2);
        p += __shfl_xor_sync(0xffffffffu, p, 1);

        float ex = __expf(p);

        if ((lane & 7) == 0)
            atomicAdd(&g_denom[(size_t)t * HH + (lane >> 3)], ex);

        red_add_v4(&g_accum[(long)t * 32 + lane],
                   make_float4(ex * xl.x, ex * xl.y, ex * xl.z, ex * xl.w));
    }
}

// ---------------- kernel 5: finalize (head mean + bias + LeakyReLU) --------
__global__ void finalize_kernel(const float* __restrict__ bias,
                                float* __restrict__ out) {
    int idx = blockIdx.x * blockDim.x + threadIdx.x;
    if (idx >= NN * OUTC) return;
    int n = idx >> 5, c = idx & 31;
    const float* acc = (const float*)g_accum;
    float sum = 0.f;
#pragma unroll
    for (int hh = 0; hh < HH; hh++)
        sum += acc[(size_t)n * HO + hh * OUTC + c] / g_denom[(size_t)n * HH + hh];
    float o = sum * 0.25f + bias[c];
    out[idx] = lrelu(o);
}

// ---------------- launch ---------------------------------------------------
extern "C" void kernel_launch(void* const* d_in, const int* in_sizes, int n_in,
                              void* d_out, int out_size) {
    const float* x     = (const float*)d_in[0];
    const int*   ei    = (const int*)  d_in[1];
    const float* eattr = (const float*)d_in[2];
    const float* Wl    = (const float*)d_in[3];
    const float* bl    = (const float*)d_in[4];
    const float* Wr    = (const float*)d_in[5];
    const float* br    = (const float*)d_in[6];
    const float* We    = (const float*)d_in[7];
    const float* att   = (const float*)d_in[8];
    const float* bias  = (const float*)d_in[9];
    float* out = (float*)d_out;

    zero_kernel<<<4096, 256>>>();
    deg_attr_kernel<<<(EE + 255) / 256, 256>>>(ei, eattr);
    gemm_xlr<<<(NN + 63) / 64, 256>>>(x, Wl, bl, Wr, br);
    edge_fused_kernel<<<444, 256>>>(ei, eattr, We, att);
    finalize_kernel<<<(NN * OUTC + 255) / 256, 256>>>(bias, out);
}

// round 4
// speedup vs baseline: 1.2971x; 1.2098x over previous
#include <cuda_runtime.h>

#define NN   50000
#define EE   800000
#define INC  128
#define OUTC 32
#define HH   4
#define EDIM 16
#define HO   128          // H*OUT
#define ENF  (EE + NN)    // edges + self loops = 850000
#define SLOPE 0.2f

// ---------------- scratch (device globals; no allocation allowed) ----------
__device__ float    g_xl[(size_t)NN * HO];       // x @ W_l + b_l   (25.6 MB)
__device__ float    g_xr[(size_t)NN * HO];       // x @ W_r + b_r   (25.6 MB)
__device__ float    g_deg[NN];                   // in-degree
__device__ float    g_asum[(size_t)NN * EDIM];   // scatter-sum of edge attrs
__device__ float    g_denom[(size_t)NN * HH];    // softmax denominators
__device__ float4   g_accum[(size_t)NN * OUTC];  // sum exp(s) * x_l[src]  (25.6 MB)
__device__ float4   g_e[(size_t)ENF * 32];       // edge projection E (435 MB)

// ---------------- helpers --------------------------------------------------
__device__ __forceinline__ float lrelu(float v) { return v > 0.f ? v : SLOPE * v; }

__device__ __forceinline__ void red_add_v4(float4* addr, float4 v) {
    asm volatile("red.global.add.v4.f32 [%0], {%1,%2,%3,%4};"
                 :: "l"(addr), "f"(v.x), "f"(v.y), "f"(v.z), "f"(v.w)
                 : "memory");
}

// ---------------- kernel 1: zero scratch -----------------------------------
__global__ void zero_kernel() {
    long i = (long)blockIdx.x * blockDim.x + threadIdx.x;
    long stride = (long)gridDim.x * blockDim.x;
    float* acc = (float*)g_accum;
    for (long j = i; j < (long)NN * HO; j += stride) acc[j] = 0.f;
    for (long j = i; j < (long)NN * HH; j += stride) g_denom[j] = 0.f;
    for (long j = i; j < (long)NN; j += stride) g_deg[j] = 0.f;
    for (long j = i; j < (long)NN * EDIM; j += stride) g_asum[j] = 0.f;
}

// ---------------- kernel 2: degree + attr scatter-sum (vectorized) ---------
__global__ void deg_attr_kernel(const int* __restrict__ ei,
                                const float* __restrict__ eattr) {
    int e = blockIdx.x * blockDim.x + threadIdx.x;
    if (e >= EE) return;
    int t = ei[EE + e];
    const float4* a4 = (const float4*)&eattr[(long)e * EDIM];
    float4* dst = &((float4*)g_asum)[(long)t * 4];
#pragma unroll
    for (int q = 0; q < 4; q++) red_add_v4(&dst[q], a4[q]);
    atomicAdd(&g_deg[t], 1.f);
}

// ---------------- kernel 3: x_l / x_r GEMMs (64-row tile, 256 threads) -----
__global__ void gemm_xlr(const float* __restrict__ x,
                         const float* __restrict__ Wl, const float* __restrict__ bl,
                         const float* __restrict__ Wr, const float* __restrict__ br) {
    __shared__ float xs[64][INC];
    int row0 = blockIdx.x * 64;
    int tid = threadIdx.x;

    const float4* x4 = (const float4*)x;
    for (int i = tid; i < 64 * 32; i += 256) {
        int r = i >> 5, c = i & 31;
        float4 v = make_float4(0.f, 0.f, 0.f, 0.f);
        if (row0 + r < NN) v = x4[(long)(row0 + r) * 32 + c];
        ((float4*)xs[r])[c] = v;
    }
    __syncthreads();

    int tx = tid & 31, ty = tid >> 5;
    float4 aL[8], aR[8];
#pragma unroll
    for (int r = 0; r < 8; r++) {
        aL[r] = make_float4(0.f, 0.f, 0.f, 0.f);
        aR[r] = make_float4(0.f, 0.f, 0.f, 0.f);
    }
    const float4* Wl4 = (const float4*)Wl;
    const float4* Wr4 = (const float4*)Wr;
    for (int k = 0; k < INC; k++) {
        float4 wl = Wl4[k * 32 + tx];
        float4 wr = Wr4[k * 32 + tx];
#pragma unroll
        for (int r = 0; r < 8; r++) {
            float xv = xs[ty + r * 8][k];
            aL[r].x = fmaf(xv, wl.x, aL[r].x); aL[r].y = fmaf(xv, wl.y, aL[r].y);
            aL[r].z = fmaf(xv, wl.z, aL[r].z); aL[r].w = fmaf(xv, wl.w, aL[r].w);
            aR[r].x = fmaf(xv, wr.x, aR[r].x); aR[r].y = fmaf(xv, wr.y, aR[r].y);
            aR[r].z = fmaf(xv, wr.z, aR[r].z); aR[r].w = fmaf(xv, wr.w, aR[r].w);
        }
    }
    float4 blv = ((const float4*)bl)[tx];
    float4 brv = ((const float4*)br)[tx];
#pragma unroll
    for (int r = 0; r < 8; r++) {
        int row = row0 + ty + r * 8;
        if (row < NN) {
            float4 ol = make_float4(aL[r].x + blv.x, aL[r].y + blv.y,
                                    aL[r].z + blv.z, aL[r].w + blv.w);
            float4 orr = make_float4(aR[r].x + brv.x, aR[r].y + brv.y,
                                     aR[r].z + brv.z, aR[r].w + brv.w);
            ((float4*)g_xl)[(long)row * 32 + tx] = ol;
            ((float4*)g_xr)[(long)row * 32 + tx] = orr;
        }
    }
}

// ---------------- kernel 4: edge projection GEMM (streaming) ---------------
// E[r] = attr_full[r] @ W_e.  Warp handles 8 consecutive rows; lane owns
// channel-quad `lane`. W_e slice lives in regs, amortized over 8 rows.
// Self-loop rows (r >= EE) use scatter-mean attrs (asum/deg) inline.
__global__ void __launch_bounds__(256)
egemm_kernel(const float* __restrict__ eattr,
             const float* __restrict__ We) {
    int lane = threadIdx.x & 31;
    const float4* We4 = (const float4*)We;
    float4 w[EDIM];
#pragma unroll
    for (int d = 0; d < EDIM; d++) w[d] = We4[d * 32 + lane];

    long base = ((long)blockIdx.x * (blockDim.x >> 5) + (threadIdx.x >> 5)) * 8;
    for (int r8 = 0; r8 < 8; r8++) {
        long row = base + r8;
        if (row >= ENF) return;
        const float4* ap4;
        float inv;
        if (row < EE) {
            ap4 = (const float4*)&eattr[row * EDIM];
            inv = 1.f;
        } else {
            int n = (int)(row - EE);
            ap4 = (const float4*)&g_asum[(size_t)n * EDIM];
            inv = 1.f / fmaxf(g_deg[n], 1.f);
        }
        float4 e = make_float4(0.f, 0.f, 0.f, 0.f);
#pragma unroll
        for (int q = 0; q < 4; q++) {
            float4 a4 = __ldg(&ap4[q]);
            float ad;
            ad = a4.x * inv;
            e.x = fmaf(ad, w[q*4+0].x, e.x); e.y = fmaf(ad, w[q*4+0].y, e.y);
            e.z = fmaf(ad, w[q*4+0].z, e.z); e.w = fmaf(ad, w[q*4+0].w, e.w);
            ad = a4.y * inv;
            e.x = fmaf(ad, w[q*4+1].x, e.x); e.y = fmaf(ad, w[q*4+1].y, e.y);
            e.z = fmaf(ad, w[q*4+1].z, e.z); e.w = fmaf(ad, w[q*4+1].w, e.w);
            ad = a4.z * inv;
            e.x = fmaf(ad, w[q*4+2].x, e.x); e.y = fmaf(ad, w[q*4+2].y, e.y);
            e.z = fmaf(ad, w[q*4+2].z, e.z); e.w = fmaf(ad, w[q*4+2].w, e.w);
            ad = a4.w * inv;
            e.x = fmaf(ad, w[q*4+3].x, e.x); e.y = fmaf(ad, w[q*4+3].y, e.y);
            e.z = fmaf(ad, w[q*4+3].z, e.z); e.w = fmaf(ad, w[q*4+3].w, e.w);
        }
        g_e[row * 32 + lane] = e;
    }
}

// ---------------- kernel 5: LIGHT edge pass --------------------------------
// One warp per edge. Gathers xl[src], xr[tgt], streams E, computes GATv2
// score, exp (no max-subtraction: alpha identical, scores bounded), scatters
// denom and exp*xl in one pass. ~35 issue slots / edge, low regs.
__global__ void __launch_bounds__(256)
edge_light_kernel(const int* __restrict__ ei,
                  const float* __restrict__ att) {
    int lane = threadIdx.x & 31;
    long ew = (long)blockIdx.x * 8 + (threadIdx.x >> 5);
    if (ew >= ENF) return;

    int s, t;
    if (ew < EE) { s = __ldg(&ei[ew]); t = __ldg(&ei[EE + ew]); }
    else         { s = t = (int)(ew - EE); }

    float4 xl = __ldg(&((const float4*)g_xl)[(long)s * 32 + lane]);
    float4 xr = __ldg(&((const float4*)g_xr)[(long)t * 32 + lane]);
    float4 e  = __ldg(&g_e[ew * 32 + lane]);
    float4 av = __ldg(&((const float4*)att)[lane]);

    float4 m = make_float4(lrelu(xl.x + xr.x + e.x), lrelu(xl.y + xr.y + e.y),
                           lrelu(xl.z + xr.z + e.z), lrelu(xl.w + xr.w + e.w));
    float p = m.x * av.x + m.y * av.y + m.z * av.z + m.w * av.w;
    p += __shfl_xor_sync(0xffffffffu, p, 4);
    p += __shfl_xor_sync(0xffffffffu, p, 2);
    p += __shfl_xor_sync(0xffffffffu, p, 1);

    float ex = __expf(p);

    if ((lane & 7) == 0)
        atomicAdd(&g_denom[(size_t)t * HH + (lane >> 3)], ex);

    red_add_v4(&g_accum[(long)t * 32 + lane],
               make_float4(ex * xl.x, ex * xl.y, ex * xl.z, ex * xl.w));
}

// ---------------- kernel 6: finalize (head mean + bias + LeakyReLU) --------
__global__ void finalize_kernel(const float* __restrict__ bias,
                                float* __restrict__ out) {
    int idx = blockIdx.x * blockDim.x + threadIdx.x;
    if (idx >= NN * OUTC) return;
    int n = idx >> 5, c = idx & 31;
    const float* acc = (const float*)g_accum;
    float sum = 0.f;
#pragma unroll
    for (int hh = 0; hh < HH; hh++)
        sum += acc[(size_t)n * HO + hh * OUTC + c] / g_denom[(size_t)n * HH + hh];
    float o = sum * 0.25f + bias[c];
    out[idx] = lrelu(o);
}

// ---------------- launch ---------------------------------------------------
extern "C" void kernel_launch(void* const* d_in, const int* in_sizes, int n_in,
                              void* d_out, int out_size) {
    const float* x     = (const float*)d_in[0];
    const int*   ei    = (const int*)  d_in[1];
    const float* eattr = (const float*)d_in[2];
    const float* Wl    = (const float*)d_in[3];
    const float* bl    = (const float*)d_in[4];
    const float* Wr    = (const float*)d_in[5];
    const float* br    = (const float*)d_in[6];
    const float* We    = (const float*)d_in[7];
    const float* att   = (const float*)d_in[8];
    const float* bias  = (const float*)d_in[9];
    float* out = (float*)d_out;

    zero_kernel<<<2048, 256>>>();
    deg_attr_kernel<<<(EE + 255) / 256, 256>>>(ei, eattr);
    gemm_xlr<<<(NN + 63) / 64, 256>>>(x, Wl, bl, Wr, br);
    // 8 warps/block * 8 rows/warp = 64 rows/block
    egemm_kernel<<<(ENF + 63) / 64, 256>>>(eattr, We);
    edge_light_kernel<<<(ENF + 7) / 8, 256>>>(ei, att);
    finalize_kernel<<<(NN * OUTC + 255) / 256, 256>>>(bias, out);
}

// round 5
// speedup vs baseline: 1.5980x; 1.2320x over previous
#include <cuda_runtime.h>
#include <cuda_fp16.h>

#define NN   50000
#define EE   800000
#define INC  128
#define OUTC 32
#define HH   4
#define EDIM 16
#define HO   128          // H*OUT
#define ENF  (EE + NN)    // edges + self loops = 850000
#define SLOPE 0.2f

// ---------------- scratch (device globals; no allocation allowed) ----------
__device__ float    g_xl[(size_t)NN * HO];       // x @ W_l + b_l   (25.6 MB)
__device__ float    g_xr[(size_t)NN * HO];       // x @ W_r + b_r   (25.6 MB)
__device__ float    g_deg[NN];                   // in-degree
__device__ float    g_asum[(size_t)NN * EDIM];   // scatter-sum of edge attrs
__device__ float    g_denom[(size_t)NN * HH];    // softmax denominators
__device__ float4   g_accum[(size_t)NN * OUTC];  // sum exp(s) * x_l[src]  (25.6 MB)
__device__ uint2    g_eh[(size_t)ENF * 32];      // edge projection E, fp16 (218 MB)

// ---------------- helpers --------------------------------------------------
__device__ __forceinline__ float lrelu(float v) { return v > 0.f ? v : SLOPE * v; }

__device__ __forceinline__ void red_add_v4(float4* addr, float4 v) {
    asm volatile("red.global.add.v4.f32 [%0], {%1,%2,%3,%4};"
                 :: "l"(addr), "f"(v.x), "f"(v.y), "f"(v.z), "f"(v.w)
                 : "memory");
}

// packed fp32x2 FMA (Blackwell FFMA2 — only reachable via PTX)
__device__ __forceinline__ unsigned long long pk2(float lo, float hi) {
    unsigned long long r;
    asm("mov.b64 %0, {%1, %2};" : "=l"(r) : "f"(lo), "f"(hi));
    return r;
}
__device__ __forceinline__ void fma2(unsigned long long& d, unsigned long long a,
                                     unsigned long long b, unsigned long long c) {
    asm("fma.rn.f32x2 %0, %1, %2, %3;" : "=l"(d) : "l"(a), "l"(b), "l"(c));
}
__device__ __forceinline__ float2 upk2(unsigned long long v) {
    float2 f;
    asm("mov.b64 {%0, %1}, %2;" : "=f"(f.x), "=f"(f.y) : "l"(v));
    return f;
}

// ---------------- kernel 1: zero scratch -----------------------------------
__global__ void zero_kernel() {
    long i = (long)blockIdx.x * blockDim.x + threadIdx.x;
    long stride = (long)gridDim.x * blockDim.x;
    float* acc = (float*)g_accum;
    for (long j = i; j < (long)NN * HO; j += stride) acc[j] = 0.f;
    for (long j = i; j < (long)NN * HH; j += stride) g_denom[j] = 0.f;
    for (long j = i; j < (long)NN; j += stride) g_deg[j] = 0.f;
    for (long j = i; j < (long)NN * EDIM; j += stride) g_asum[j] = 0.f;
}

// ---------------- kernel 2: degree + attr scatter-sum (vectorized) ---------
__global__ void deg_attr_kernel(const int* __restrict__ ei,
                                const float* __restrict__ eattr) {
    int e = blockIdx.x * blockDim.x + threadIdx.x;
    if (e >= EE) return;
    int t = ei[EE + e];
    const float4* a4 = (const float4*)&eattr[(long)e * EDIM];
    float4* dst = &((float4*)g_asum)[(long)t * 4];
#pragma unroll
    for (int q = 0; q < 4; q++) red_add_v4(&dst[q], a4[q]);
    atomicAdd(&g_deg[t], 1.f);
}

// ---------------- kernel 3: x_l / x_r GEMMs with FFMA2 ---------------------
__global__ void gemm_xlr(const float* __restrict__ x,
                         const float* __restrict__ Wl, const float* __restrict__ bl,
                         const float* __restrict__ Wr, const float* __restrict__ br) {
    __shared__ float xs[64][INC];
    int row0 = blockIdx.x * 64;
    int tid = threadIdx.x;

    const float4* x4 = (const float4*)x;
    for (int i = tid; i < 64 * 32; i += 256) {
        int r = i >> 5, c = i & 31;
        float4 v = make_float4(0.f, 0.f, 0.f, 0.f);
        if (row0 + r < NN) v = x4[(long)(row0 + r) * 32 + c];
        ((float4*)xs[r])[c] = v;
    }
    __syncthreads();

    int tx = tid & 31, ty = tid >> 5;        // tx: channel quad, ty: row phase
    unsigned long long accL[8][2], accR[8][2];
    unsigned long long z2 = pk2(0.f, 0.f);
#pragma unroll
    for (int r = 0; r < 8; r++) {
        accL[r][0] = z2; accL[r][1] = z2;
        accR[r][0] = z2; accR[r][1] = z2;
    }
    const float4* Wl4 = (const float4*)Wl;
    const float4* Wr4 = (const float4*)Wr;
    for (int k = 0; k < INC; k++) {
        float4 wl = Wl4[k * 32 + tx];
        float4 wr = Wr4[k * 32 + tx];
        unsigned long long wl0 = pk2(wl.x, wl.y), wl1 = pk2(wl.z, wl.w);
        unsigned long long wr0 = pk2(wr.x, wr.y), wr1 = pk2(wr.z, wr.w);
#pragma unroll
        for (int r = 0; r < 8; r++) {
            float xv = xs[ty + r * 8][k];
            unsigned long long xv2 = pk2(xv, xv);
            fma2(accL[r][0], xv2, wl0, accL[r][0]);
            fma2(accL[r][1], xv2, wl1, accL[r][1]);
            fma2(accR[r][0], xv2, wr0, accR[r][0]);
            fma2(accR[r][1], xv2, wr1, accR[r][1]);
        }
    }
    float4 blv = ((const float4*)bl)[tx];
    float4 brv = ((const float4*)br)[tx];
#pragma unroll
    for (int r = 0; r < 8; r++) {
        int row = row0 + ty + r * 8;
        if (row < NN) {
            float2 l0 = upk2(accL[r][0]), l1 = upk2(accL[r][1]);
            float2 r0 = upk2(accR[r][0]), r1 = upk2(accR[r][1]);
            ((float4*)g_xl)[(long)row * 32 + tx] =
                make_float4(l0.x + blv.x, l0.y + blv.y, l1.x + blv.z, l1.y + blv.w);
            ((float4*)g_xr)[(long)row * 32 + tx] =
                make_float4(r0.x + brv.x, r0.y + brv.y, r1.x + brv.z, r1.y + brv.w);
        }
    }
}

// ---------------- kernel 4: edge projection GEMM (FFMA2, fp16 out) ---------
// E[r] = attr_full[r] @ W_e, stored fp16. Warp handles 8 rows; lane owns
// channel-quad `lane` (2 packed f32x2 accumulators). Self-loop rows use
// scatter-mean attrs inline.
__global__ void __launch_bounds__(256)
egemm_kernel(const float* __restrict__ eattr,
             const float* __restrict__ We) {
    int lane = threadIdx.x & 31;
    const float4* We4 = (const float4*)We;
    unsigned long long w2[EDIM][2];
#pragma unroll
    for (int d = 0; d < EDIM; d++) {
        float4 q = We4[d * 32 + lane];
        w2[d][0] = pk2(q.x, q.y);
        w2[d][1] = pk2(q.z, q.w);
    }
    unsigned long long z2 = pk2(0.f, 0.f);

    long base = ((long)blockIdx.x * 8 + (threadIdx.x >> 5)) * 8;
#pragma unroll 2
    for (int r8 = 0; r8 < 8; r8++) {
        long row = base + r8;
        if (row >= ENF) break;
        const float4* ap4;
        float inv;
        if (row < EE) {
            ap4 = (const float4*)&eattr[row * EDIM];
            inv = 1.f;
        } else {
            int n = (int)(row - EE);
            ap4 = (const float4*)&g_asum[(size_t)n * EDIM];
            inv = 1.f / fmaxf(g_deg[n], 1.f);
        }
        float a[EDIM];
#pragma unroll
        for (int q = 0; q < 4; q++) {
            float4 a4 = __ldg(&ap4[q]);
            a[q*4+0] = a4.x * inv; a[q*4+1] = a4.y * inv;
            a[q*4+2] = a4.z * inv; a[q*4+3] = a4.w * inv;
        }
        unsigned long long e0 = z2, e1 = z2;
#pragma unroll
        for (int d = 0; d < EDIM; d++) {
            unsigned long long ad2 = pk2(a[d], a[d]);
            fma2(e0, ad2, w2[d][0], e0);
            fma2(e1, ad2, w2[d][1], e1);
        }
        float2 f0 = upk2(e0), f1 = upk2(e1);
        __half2 h0 = __float22half2_rn(make_float2(f0.x, f0.y));
        __half2 h1 = __float22half2_rn(make_float2(f1.x, f1.y));
        uint2 out;
        out.x = *(unsigned*)&h0;
        out.y = *(unsigned*)&h1;
        g_eh[row * 32 + lane] = out;
    }
}

// ---------------- kernel 5: LIGHT edge pass --------------------------------
// One warp per edge. Gathers xl[src], xr[tgt], streams fp16 E, computes GATv2
// score, exp (no max-subtraction: alpha identical, scores bounded), scatters
// denom and exp*xl in one pass.
__global__ void __launch_bounds__(256)
edge_light_kernel(const int* __restrict__ ei,
                  const float* __restrict__ att) {
    int lane = threadIdx.x & 31;
    long ew = (long)blockIdx.x * 8 + (threadIdx.x >> 5);
    if (ew >= ENF) return;

    int s, t;
    if (ew < EE) { s = __ldg(&ei[ew]); t = __ldg(&ei[EE + ew]); }
    else         { s = t = (int)(ew - EE); }

    float4 xl = __ldg(&((const float4*)g_xl)[(long)s * 32 + lane]);
    float4 xr = __ldg(&((const float4*)g_xr)[(long)t * 32 + lane]);
    uint2 eh  = __ldg(&g_eh[ew * 32 + lane]);
    float2 e0 = __half22float2(*(__half2*)&eh.x);
    float2 e1 = __half22float2(*(__half2*)&eh.y);
    float4 av = __ldg(&((const float4*)att)[lane]);

    float4 m = make_float4(lrelu(xl.x + xr.x + e0.x), lrelu(xl.y + xr.y + e0.y),
                           lrelu(xl.z + xr.z + e1.x), lrelu(xl.w + xr.w + e1.y));
    float p = m.x * av.x + m.y * av.y + m.z * av.z + m.w * av.w;
    p += __shfl_xor_sync(0xffffffffu, p, 4);
    p += __shfl_xor_sync(0xffffffffu, p, 2);
    p += __shfl_xor_sync(0xffffffffu, p, 1);

    float ex = __expf(p);

    if ((lane & 7) == 0)
        atomicAdd(&g_denom[(size_t)t * HH + (lane >> 3)], ex);

    red_add_v4(&g_accum[(long)t * 32 + lane],
               make_float4(ex * xl.x, ex * xl.y, ex * xl.z, ex * xl.w));
}

// ---------------- kernel 6: finalize (head mean + bias + LeakyReLU) --------
__global__ void finalize_kernel(const float* __restrict__ bias,
                                float* __restrict__ out) {
    int idx = blockIdx.x * blockDim.x + threadIdx.x;
    if (idx >= NN * OUTC) return;
    int n = idx >> 5, c = idx & 31;
    const float* acc = (const float*)g_accum;
    float sum = 0.f;
#pragma unroll
    for (int hh = 0; hh < HH; hh++)
        sum += acc[(size_t)n * HO + hh * OUTC + c] / g_denom[(size_t)n * HH + hh];
    float o = sum * 0.25f + bias[c];
    out[idx] = lrelu(o);
}

// ---------------- launch ---------------------------------------------------
extern "C" void kernel_launch(void* const* d_in, const int* in_sizes, int n_in,
                              void* d_out, int out_size) {
    const float* x     = (const float*)d_in[0];
    const int*   ei    = (const int*)  d_in[1];
    const float* eattr = (const float*)d_in[2];
    const float* Wl    = (const float*)d_in[3];
    const float* bl    = (const float*)d_in[4];
    const float* Wr    = (const float*)d_in[5];
    const float* br    = (const float*)d_in[6];
    const float* We    = (const float*)d_in[7];
    const float* att   = (const float*)d_in[8];
    const float* bias  = (const float*)d_in[9];
    float* out = (float*)d_out;

    zero_kernel<<<2048, 256>>>();
    deg_attr_kernel<<<(EE + 255) / 256, 256>>>(ei, eattr);
    gemm_xlr<<<(NN + 63) / 64, 256>>>(x, Wl, bl, Wr, br);
    egemm_kernel<<<(ENF + 63) / 64, 256>>>(eattr, We);   // 64 rows/block
    edge_light_kernel<<<(ENF + 7) / 8, 256>>>(ei, att);
    finalize_kernel<<<(NN * OUTC + 255) / 256, 256>>>(bias, out);
}

// round 6
// speedup vs baseline: 2.1444x; 1.3419x over previous
#include <cuda_runtime.h>
#include <cuda_fp16.h>

#define NN   50000
#define EE   800000
#define INC  128
#define OUTC 32
#define HH   4
#define EDIM 16
#define HO   128          // H*OUT
#define ENF  (EE + NN)    // edges + self loops = 850000 (divisible by 16)
#define NBATCH (ENF / 16) // 53125 warp batches
#define SLOPE 0.2f

// ---------------- scratch (device globals; no allocation allowed) ----------
__device__ float    g_xl[(size_t)NN * HO];       // x @ W_l + b_l   (25.6 MB)
__device__ float    g_xr[(size_t)NN * HO];       // x @ W_r + b_r   (25.6 MB)
__device__ float    g_deg[NN];                   // in-degree
__device__ float    g_asum[(size_t)NN * EDIM];   // scatter-sum of edge attrs
__device__ float    g_denom[(size_t)NN * HH];    // softmax denominators
__device__ float4   g_accum[(size_t)NN * OUTC];  // sum exp(s) * x_l[src]  (25.6 MB)
// E in mma-fragment permuted order: [batch][tile 0..15][sel 0..1][lane 0..31]
__device__ unsigned g_eperm[(size_t)NBATCH * 1024];   // fp16x2 words (217.6 MB)

// ---------------- helpers --------------------------------------------------
__device__ __forceinline__ float lrelu(float v) { return v > 0.f ? v : SLOPE * v; }

__device__ __forceinline__ void red_add_v4(float4* addr, float4 v) {
    asm volatile("red.global.add.v4.f32 [%0], {%1,%2,%3,%4};"
                 :: "l"(addr), "f"(v.x), "f"(v.y), "f"(v.z), "f"(v.w)
                 : "memory");
}

// pack two f32 into f16x2: lo -> bits[15:0], hi -> bits[31:16]
__device__ __forceinline__ unsigned pack_h2(float hi, float lo) {
    unsigned r;
    asm("cvt.rn.f16x2.f32 %0, %1, %2;" : "=r"(r) : "f"(hi), "f"(lo));
    return r;
}

// packed fp32x2 FMA (Blackwell FFMA2 — only reachable via PTX)
__device__ __forceinline__ unsigned long long pk2(float lo, float hi) {
    unsigned long long r;
    asm("mov.b64 %0, {%1, %2};" : "=l"(r) : "f"(lo), "f"(hi));
    return r;
}
__device__ __forceinline__ void fma2(unsigned long long& d, unsigned long long a,
                                     unsigned long long b, unsigned long long c) {
    asm("fma.rn.f32x2 %0, %1, %2, %3;" : "=l"(d) : "l"(a), "l"(b), "l"(c));
}
__device__ __forceinline__ float2 upk2(unsigned long long v) {
    float2 f;
    asm("mov.b64 {%0, %1}, %2;" : "=f"(f.x), "=f"(f.y) : "l"(v));
    return f;
}

// ---------------- kernel 1: zero scratch -----------------------------------
__global__ void zero_kernel() {
    long i = (long)blockIdx.x * blockDim.x + threadIdx.x;
    long stride = (long)gridDim.x * blockDim.x;
    float* acc = (float*)g_accum;
    for (long j = i; j < (long)NN * HO; j += stride) acc[j] = 0.f;
    for (long j = i; j < (long)NN * HH; j += stride) g_denom[j] = 0.f;
    for (long j = i; j < (long)NN; j += stride) g_deg[j] = 0.f;
    for (long j = i; j < (long)NN * EDIM; j += stride) g_asum[j] = 0.f;
}

// ---------------- kernel 2: degree + attr scatter-sum (vectorized) ---------
__global__ void deg_attr_kernel(const int* __restrict__ ei,
                                const float* __restrict__ eattr) {
    int e = blockIdx.x * blockDim.x + threadIdx.x;
    if (e >= EE) return;
    int t = ei[EE + e];
    const float4* a4 = (const float4*)&eattr[(long)e * EDIM];
    float4* dst = &((float4*)g_asum)[(long)t * 4];
#pragma unroll
    for (int q = 0; q < 4; q++) red_add_v4(&dst[q], a4[q]);
    atomicAdd(&g_deg[t], 1.f);
}

// ---------------- kernel 3: x_l / x_r GEMMs with FFMA2 ---------------------
__global__ void gemm_xlr(const float* __restrict__ x,
                         const float* __restrict__ Wl, const float* __restrict__ bl,
                         const float* __restrict__ Wr, const float* __restrict__ br) {
    __shared__ float xs[64][INC];
    int row0 = blockIdx.x * 64;
    int tid = threadIdx.x;

    const float4* x4 = (const float4*)x;
    for (int i = tid; i < 64 * 32; i += 256) {
        int r = i >> 5, c = i & 31;
        float4 v = make_float4(0.f, 0.f, 0.f, 0.f);
        if (row0 + r < NN) v = x4[(long)(row0 + r) * 32 + c];
        ((float4*)xs[r])[c] = v;
    }
    __syncthreads();

    int tx = tid & 31, ty = tid >> 5;
    unsigned long long accL[8][2], accR[8][2];
    unsigned long long z2 = pk2(0.f, 0.f);
#pragma unroll
    for (int r = 0; r < 8; r++) {
        accL[r][0] = z2; accL[r][1] = z2;
        accR[r][0] = z2; accR[r][1] = z2;
    }
    const float4* Wl4 = (const float4*)Wl;
    const float4* Wr4 = (const float4*)Wr;
    for (int k = 0; k < INC; k++) {
        float4 wl = Wl4[k * 32 + tx];
        float4 wr = Wr4[k * 32 + tx];
        unsigned long long wl0 = pk2(wl.x, wl.y), wl1 = pk2(wl.z, wl.w);
        unsigned long long wr0 = pk2(wr.x, wr.y), wr1 = pk2(wr.z, wr.w);
#pragma unroll
        for (int r = 0; r < 8; r++) {
            float xv = xs[ty + r * 8][k];
            unsigned long long xv2 = pk2(xv, xv);
            fma2(accL[r][0], xv2, wl0, accL[r][0]);
            fma2(accL[r][1], xv2, wl1, accL[r][1]);
            fma2(accR[r][0], xv2, wr0, accR[r][0]);
            fma2(accR[r][1], xv2, wr1, accR[r][1]);
        }
    }
    float4 blv = ((const float4*)bl)[tx];
    float4 brv = ((const float4*)br)[tx];
#pragma unroll
    for (int r = 0; r < 8; r++) {
        int row = row0 + ty + r * 8;
        if (row < NN) {
            float2 l0 = upk2(accL[r][0]), l1 = upk2(accL[r][1]);
            float2 r0 = upk2(accR[r][0]), r1 = upk2(accR[r][1]);
            ((float4*)g_xl)[(long)row * 32 + tx] =
                make_float4(l0.x + blv.x, l0.y + blv.y, l1.x + blv.z, l1.y + blv.w);
            ((float4*)g_xr)[(long)row * 32 + tx] =
                make_float4(r0.x + brv.x, r0.y + brv.y, r1.x + brv.z, r1.y + brv.w);
        }
    }
}

// ---------------- kernel 4: edge projection via tensor cores ---------------
// Each warp computes a 16-row x 128-col tile of E = attr_full @ W_e using
// 16x mma.sync.m16n8k16 (fp16 in, fp32 acc). W_e B-fragments cached in regs.
// E is stored fp16 in FRAGMENT-PERMUTED order (no epilogue shuffle needed):
//   word index = batch*1024 + tile*64 + sel*32 + srclane
// where sel 0/1 = rows grp / grp+8.  Self-loop rows use scatter-mean attrs.
__global__ void __launch_bounds__(256)
egemm_mma_kernel(const float* __restrict__ eattr,
                 const float* __restrict__ We) {
    int lane = threadIdx.x & 31;
    long warpid = (long)blockIdx.x * 8 + (threadIdx.x >> 5);
    if (warpid >= NBATCH) return;
    int grp = lane >> 2, ctg = lane & 3;

    // B fragments for all 16 n-tiles: b0 = k rows 2ctg,2ctg+1; b1 = +8
    unsigned b0[16], b1[16];
#pragma unroll
    for (int t = 0; t < 16; t++) {
        int col = t * 8 + grp;
        float x0 = __ldg(&We[(2 * ctg) * HO + col]);
        float x1 = __ldg(&We[(2 * ctg + 1) * HO + col]);
        float x2 = __ldg(&We[(2 * ctg + 8) * HO + col]);
        float x3 = __ldg(&We[(2 * ctg + 9) * HO + col]);
        b0[t] = pack_h2(x1, x0);
        b1[t] = pack_h2(x3, x2);
    }

    // A fragments: rows base+grp (a0,a2) and base+grp+8 (a1,a3)
    long base = warpid * 16;
    unsigned a0, a1, a2, a3;
    {
        long row = base + grp;
        const float* p; float inv = 1.f;
        if (row < EE) { p = &eattr[row * EDIM]; }
        else { int n = (int)(row - EE); p = &g_asum[(size_t)n * EDIM];
               inv = 1.f / fmaxf(g_deg[n], 1.f); }
        float2 lo = *(const float2*)(p + 2 * ctg);
        float2 hi = *(const float2*)(p + 2 * ctg + 8);
        a0 = pack_h2(lo.y * inv, lo.x * inv);
        a2 = pack_h2(hi.y * inv, hi.x * inv);
    }
    {
        long row = base + grp + 8;
        const float* p; float inv = 1.f;
        if (row < EE) { p = &eattr[row * EDIM]; }
        else { int n = (int)(row - EE); p = &g_asum[(size_t)n * EDIM];
               inv = 1.f / fmaxf(g_deg[n], 1.f); }
        float2 lo = *(const float2*)(p + 2 * ctg);
        float2 hi = *(const float2*)(p + 2 * ctg + 8);
        a1 = pack_h2(lo.y * inv, lo.x * inv);
        a3 = pack_h2(hi.y * inv, hi.x * inv);
    }

    unsigned* outp = g_eperm + (size_t)warpid * 1024;
    float z = 0.f;
#pragma unroll
    for (int t = 0; t < 16; t++) {
        float d0, d1, d2, d3;
        asm volatile(
            "mma.sync.aligned.m16n8k16.row.col.f32.f16.f16.f32 "
            "{%0,%1,%2,%3}, {%4,%5,%6,%7}, {%8,%9}, {%10,%10,%10,%10};"
            : "=f"(d0), "=f"(d1), "=f"(d2), "=f"(d3)
            : "r"(a0), "r"(a1), "r"(a2), "r"(a3),
              "r"(b0[t]), "r"(b1[t]), "f"(z));
        outp[t * 64 + lane]      = pack_h2(d1, d0);   // rows grp   (sel 0)
        outp[t * 64 + 32 + lane] = pack_h2(d3, d2);   // rows grp+8 (sel 1)
    }
}

// ---------------- kernel 5: LIGHT edge pass --------------------------------
// One warp per edge; lane owns channel quad 4*lane..4*lane+3. Reads E from
// the fragment-permuted buffer with a single LDG.64 per lane.
__global__ void __launch_bounds__(256)
edge_light_kernel(const int* __restrict__ ei,
                  const float* __restrict__ att) {
    int lane = threadIdx.x & 31;
    long ew = (long)blockIdx.x * 8 + (threadIdx.x >> 5);
    if (ew >= ENF) return;

    int s, t;
    if (ew < EE) { s = __ldg(&ei[ew]); t = __ldg(&ei[EE + ew]); }
    else         { s = t = (int)(ew - EE); }

    float4 xl = __ldg(&((const float4*)g_xl)[(long)s * 32 + lane]);
    float4 xr = __ldg(&((const float4*)g_xr)[(long)t * 32 + lane]);

    // E from fragment-permuted layout
    long batch = ew >> 4;
    int g16 = (int)(ew & 15);
    int sel = g16 >> 3, gval = g16 & 7;
    int tile = lane >> 1, q = lane & 1;
    uint2 ev = __ldg((const uint2*)(g_eperm + (size_t)batch * 1024 +
                                   tile * 64 + sel * 32 + 4 * gval + 2 * q));
    float2 e01 = __half22float2(*(__half2*)&ev.x);
    float2 e23 = __half22float2(*(__half2*)&ev.y);

    float4 av = __ldg(&((const float4*)att)[lane]);

    float4 m = make_float4(lrelu(xl.x + xr.x + e01.x), lrelu(xl.y + xr.y + e01.y),
                           lrelu(xl.z + xr.z + e23.x), lrelu(xl.w + xr.w + e23.y));
    float p = m.x * av.x + m.y * av.y + m.z * av.z + m.w * av.w;
    p += __shfl_xor_sync(0xffffffffu, p, 4);
    p += __shfl_xor_sync(0xffffffffu, p, 2);
    p += __shfl_xor_sync(0xffffffffu, p, 1);

    float ex = __expf(p);

    if ((lane & 7) == 0)
        atomicAdd(&g_denom[(size_t)t * HH + (lane >> 3)], ex);

    red_add_v4(&g_accum[(long)t * 32 + lane],
               make_float4(ex * xl.x, ex * xl.y, ex * xl.z, ex * xl.w));
}

// ---------------- kernel 6: finalize (head mean + bias + LeakyReLU) --------
__global__ void finalize_kernel(const float* __restrict__ bias,
                                float* __restrict__ out) {
    int idx = blockIdx.x * blockDim.x + threadIdx.x;
    if (idx >= NN * OUTC) return;
    int n = idx >> 5, c = idx & 31;
    const float* acc = (const float*)g_accum;
    float sum = 0.f;
#pragma unroll
    for (int hh = 0; hh < HH; hh++)
        sum += acc[(size_t)n * HO + hh * OUTC + c] / g_denom[(size_t)n * HH + hh];
    float o = sum * 0.25f + bias[c];
    out[idx] = lrelu(o);
}

// ---------------- launch ---------------------------------------------------
extern "C" void kernel_launch(void* const* d_in, const int* in_sizes, int n_in,
                              void* d_out, int out_size) {
    const float* x     = (const float*)d_in[0];
    const int*   ei    = (const int*)  d_in[1];
    const float* eattr = (const float*)d_in[2];
    const float* Wl    = (const float*)d_in[3];
    const float* bl    = (const float*)d_in[4];
    const float* Wr    = (const float*)d_in[5];
    const float* br    = (const float*)d_in[6];
    const float* We    = (const float*)d_in[7];
    const float* att   = (const float*)d_in[8];
    const float* bias  = (const float*)d_in[9];
    float* out = (float*)d_out;

    zero_kernel<<<2048, 256>>>();
    deg_attr_kernel<<<(EE + 255) / 256, 256>>>(ei, eattr);
    gemm_xlr<<<(NN + 63) / 64, 256>>>(x, Wl, bl, Wr, br);
    egemm_mma_kernel<<<(NBATCH + 7) / 8, 256>>>(eattr, We);  // 8 warps/block
    edge_light_kernel<<<(ENF + 7) / 8, 256>>>(ei, att);
    finalize_kernel<<<(NN * OUTC + 255) / 256, 256>>>(bias, out);
}